// round 11
// baseline (speedup 1.0000x reference)
#include <cuda_runtime.h>
#include <math.h>
#include <stdint.h>

#define Hd 128
#define Ld 200
#define DTd 768
#define DId 512
#define NTOK 25600
#define TB 64
#define NTH 512

// smem layout (u32 units)
#define O_WH0 0
#define O_WL0 2560
#define O_WH1 5120
#define O_WL1 7680
#define O_AH0 10240
#define O_AL0 11520
#define O_AH1 12800
#define O_AL1 14080
#define O_XH 15360
#define O_XL 19712
#define O_YH 24064
#define O_YL 28416
#define O_GT 32768
#define O_GI 33280
#define O_ID 33792
#define SMEMU 33856   // 135424 B, 1 CTA/SM

__device__ __forceinline__ uint32_t cvt2(float lo, float hi) {
    uint32_t r;
    asm("cvt.rn.bf16x2.f32 %0, %1, %2;" : "=r"(r) : "f"(hi), "f"(lo));
    return r;
}
__device__ __forceinline__ float blo(uint32_t u) { return __uint_as_float(u << 16); }
__device__ __forceinline__ float bhi(uint32_t u) { return __uint_as_float(u & 0xffff0000u); }

__device__ __forceinline__ void splitq(float4 a, float4 b, uint4& h, uint4& l) {
    h.x = cvt2(a.x, a.y); l.x = cvt2(a.x - blo(h.x), a.y - bhi(h.x));
    h.y = cvt2(a.z, a.w); l.y = cvt2(a.z - blo(h.y), a.w - bhi(h.y));
    h.z = cvt2(b.x, b.y); l.z = cvt2(b.x - blo(h.z), b.y - bhi(h.z));
    h.w = cvt2(b.z, b.w); l.w = cvt2(b.z - blo(h.w), b.w - bhi(h.w));
}

__device__ __forceinline__ void MMA(float* d, uint32_t a0, uint32_t a1, uint32_t a2, uint32_t a3,
                                    uint32_t b0, uint32_t b1) {
    asm volatile("mma.sync.aligned.m16n8k16.row.col.f32.bf16.bf16.f32 "
                 "{%0,%1,%2,%3},{%4,%5,%6,%7},{%8,%9},{%0,%1,%2,%3};"
                 : "+f"(d[0]), "+f"(d[1]), "+f"(d[2]), "+f"(d[3])
                 : "r"(a0), "r"(a1), "r"(a2), "r"(a3), "r"(b0), "r"(b1));
}

__device__ __forceinline__ void zeroD(float D[4][4]) {
#pragma unroll
    for (int n = 0; n < 4; ++n)
#pragma unroll
        for (int j = 0; j < 4; ++j) D[n][j] = 0.f;
}

__device__ __forceinline__ void w_ldg(const float* __restrict__ W, int ldw, int kc,
                                      int tid, float4 v[2]) {
    int h = tid >> 2, q = tid & 3;
    const float* p = W + (long)h * ldw + kc + q * 8;
    v[0] = *(const float4*)p;
    v[1] = *(const float4*)(p + 4);
}
__device__ __forceinline__ void w_sts(uint32_t* sWh, uint32_t* sWl, int tid, const float4 v[2]) {
    int h = tid >> 2, q = tid & 3;
    uint4 hi, lo;
    splitq(v[0], v[1], hi, lo);
    *(uint4*)(sWh + h * 20 + q * 4) = hi;
    *(uint4*)(sWl + h * 20 + q * 4) = lo;
}
__device__ __forceinline__ void ga_ldg(const float* __restrict__ T, int ldw, int kc,
                                       const int* sids, int tid, float4 v[2]) {
    if (tid < 256) {
        int tok = tid >> 2, q = tid & 3;
        const float* p = T + (long)sids[tok] * ldw + kc + q * 8;
        v[0] = *(const float4*)p;
        v[1] = *(const float4*)(p + 4);
    }
}
__device__ __forceinline__ void ga_sts(uint32_t* sAh, uint32_t* sAl, int tid, const float4 v[2]) {
    if (tid < 256) {
        int tok = tid >> 2, q = tid & 3;
        uint4 hi, lo;
        splitq(v[0], v[1], hi, lo);
        *(uint4*)(sAh + tok * 20 + q * 4) = hi;
        *(uint4*)(sAl + tok * 20 + q * 4) = lo;
    }
}

// one KC=32 chunk: warp tile 16h x 32tok, 3-limb
__device__ __forceinline__ void mma_chunk(const uint32_t* __restrict__ Wh, const uint32_t* __restrict__ Wl,
                                          const uint32_t* __restrict__ Bh, const uint32_t* __restrict__ Bl,
                                          int bst, int lane, float D[4][4]) {
    int g = lane >> 2, q = lane & 3;
#pragma unroll
    for (int kt = 0; kt < 2; ++kt) {
        int o = kt * 8 + q;
        uint32_t ah0 = Wh[g * 20 + o], ah1 = Wh[(g + 8) * 20 + o];
        uint32_t ah2 = Wh[g * 20 + o + 4], ah3 = Wh[(g + 8) * 20 + o + 4];
        uint32_t al0 = Wl[g * 20 + o], al1 = Wl[(g + 8) * 20 + o];
        uint32_t al2 = Wl[g * 20 + o + 4], al3 = Wl[(g + 8) * 20 + o + 4];
#pragma unroll
        for (int nt = 0; nt < 4; ++nt) {
            const uint32_t* bp = Bh + (nt * 8 + g) * bst + o;
            const uint32_t* bq = Bl + (nt * 8 + g) * bst + o;
            uint32_t b0 = bp[0], b1 = bp[4];
            uint32_t c0 = bq[0], c1 = bq[4];
            MMA(D[nt], ah0, ah1, ah2, ah3, b0, b1);
            MMA(D[nt], ah0, ah1, ah2, ah3, c0, c1);
            MMA(D[nt], al0, al1, al2, al3, b0, b1);
        }
    }
}

__device__ __forceinline__ void stage_D(float* sWf, float D[4][4], int lane, int hb, int tb) {
    int g = lane >> 2, q = lane & 3;
#pragma unroll
    for (int nt = 0; nt < 4; ++nt) {
        int t0 = tb + nt * 8 + 2 * q;
        float* p0 = sWf + t0 * 132 + hb + g;
        float* p1 = sWf + (t0 + 1) * 132 + hb + g;
        p0[0] = D[nt][0]; p1[0] = D[nt][1]; p0[8] = D[nt][2]; p1[8] = D[nt][3];
    }
}

__device__ __forceinline__ void route8(float* g) {
    float m = g[0];
#pragma unroll
    for (int e = 1; e < 8; ++e) m = fmaxf(m, g[e]);
    float ex[8]; float s = 0.f;
#pragma unroll
    for (int e = 0; e < 8; ++e) { ex[e] = __expf(g[e] - m); s += ex[e]; }
    float inv = 1.f / s;
#pragma unroll
    for (int e = 0; e < 8; ++e) ex[e] *= inv;
    int i1 = 0; float w1 = ex[0];
#pragma unroll
    for (int e = 1; e < 8; ++e) if (ex[e] > w1) { w1 = ex[e]; i1 = e; }
    int i2 = -1; float w2 = -1.f;
#pragma unroll
    for (int e = 0; e < 8; ++e) if (e != i1 && ex[e] > w2) { w2 = ex[e]; i2 = e; }
    float den = 1.f / (w1 + w2 + 1e-8f);
#pragma unroll
    for (int e = 0; e < 8; ++e)
        g[e] = (e == i1) ? w1 * den : ((e == i2) ? w2 * den : 0.f);
}

__global__ __launch_bounds__(NTH, 1)
void sasrec_mma_kernel(
    const int*   __restrict__ input_ids,
    const float* __restrict__ t_noise,   const float* __restrict__ i_noise,
    const float* __restrict__ item_table,const float* __restrict__ pos_table,
    const float* __restrict__ text_table,const float* __restrict__ img_table,
    const float* __restrict__ fc_text_w, const float* __restrict__ fc_text_b,
    const float* __restrict__ fc_img_w,  const float* __restrict__ fc_img_b,
    const float* __restrict__ ln_w,      const float* __restrict__ ln_b,
    const float* __restrict__ mu_t_w,    const float* __restrict__ mu_t_b,
    const float* __restrict__ sg_t_w,    const float* __restrict__ sg_t_b,
    const float* __restrict__ mu_i_w,    const float* __restrict__ mu_i_b,
    const float* __restrict__ sg_i_w,    const float* __restrict__ sg_i_b,
    const float* __restrict__ gate_w,    const float* __restrict__ gate_b,
    const float* __restrict__ texp_w,    const float* __restrict__ texp_b,
    const float* __restrict__ iexp_w,    const float* __restrict__ iexp_b,
    const float* __restrict__ fus_w,     const float* __restrict__ fus_b,
    const float* __restrict__ fus_ln_w,  const float* __restrict__ fus_ln_b,
    float*       __restrict__ out)
{
    extern __shared__ uint32_t su[];
    float* sWf = (float*)su;              // staging overlaps W buffers (used only between GEMMs)
    uint32_t *sXh = su + O_XH, *sXl = su + O_XL;
    uint32_t *sYh = su + O_YH, *sYl = su + O_YL;
    float *sgt = (float*)(su + O_GT), *sgi = (float*)(su + O_GI);
    int* sids = (int*)(su + O_ID);

    const int tid = threadIdx.x, lane = tid & 31, wid = tid >> 5;
    const int hb = (wid & 7) * 16;
    const int tb = (wid >> 3) * 32;
    const int n0 = blockIdx.x * TB;
    const int tok = tid >> 3, pq = tid & 7;

    if (tid < TB) sids[tid] = input_ids[n0 + tid];
    __syncthreads();

    float D[4][4];
    float4 wv[2], av[2];

#define WHB(i) (su + ((i) ? O_WH1 : O_WH0))
#define WLB(i) (su + ((i) ? O_WL1 : O_WL0))
#define AHB(i) (su + ((i) ? O_AH1 : O_AH0))
#define ALB(i) (su + ((i) ? O_AL1 : O_AL0))

    // ===== stages 1-2: modality embeddings =====
#pragma unroll 1
    for (int mod = 0; mod < 2; ++mod) {
        const float* tbl = mod ? img_table : text_table;
        const float* Wg  = mod ? fc_img_w : fc_text_w;
        const float* Bb  = mod ? fc_img_b : fc_text_b;
        const int Kd = mod ? DId : DTd;
        uint32_t* szh = mod ? sYh : sXh;
        uint32_t* szl = mod ? sYl : sXl;
        zeroD(D);
        w_ldg(Wg, Kd, 0, tid, wv);
        ga_ldg(tbl, Kd, 0, sids, tid, av);
        w_sts(WHB(0), WLB(0), tid, wv);
        ga_sts(AHB(0), ALB(0), tid, av);
        const int nck = Kd / 32;
#pragma unroll 1
        for (int c = 0; c < nck; ++c) {
            int cur = c & 1, nxt = cur ^ 1;
            if (c + 1 < nck) {
                w_ldg(Wg, Kd, (c + 1) * 32, tid, wv);
                ga_ldg(tbl, Kd, (c + 1) * 32, sids, tid, av);
            }
            __syncthreads();
            if (c + 1 < nck) {
                w_sts(WHB(nxt), WLB(nxt), tid, wv);
                ga_sts(AHB(nxt), ALB(nxt), tid, av);
            }
            mma_chunk(WHB(cur) + hb * 20, WLB(cur) + hb * 20,
                      AHB(cur) + tb * 20, ALB(cur) + tb * 20, 20, lane, D);
        }
        __syncthreads();
        stage_D(sWf, D, lane, hb, tb);
        __syncthreads();
        {
            float v[16]; float ss = 0.f;
#pragma unroll
            for (int j = 0; j < 4; ++j) {
                float4 a = *(const float4*)(sWf + tok * 132 + pq * 16 + j * 4);
                float4 b = *(const float4*)(Bb + pq * 16 + j * 4);
                v[j*4+0] = a.x + b.x; v[j*4+1] = a.y + b.y;
                v[j*4+2] = a.z + b.z; v[j*4+3] = a.w + b.w;
#pragma unroll
                for (int k = 0; k < 4; ++k) ss += v[j*4+k] * v[j*4+k];
            }
            ss += __shfl_xor_sync(0xffffffffu, ss, 1);
            ss += __shfl_xor_sync(0xffffffffu, ss, 2);
            ss += __shfl_xor_sync(0xffffffffu, ss, 4);
            float sc = 1.f / fmaxf(sqrtf(ss), 1e-12f);
#pragma unroll
            for (int j = 0; j < 16; ++j) v[j] *= sc;
#pragma unroll
            for (int j = 0; j < 2; ++j) {
                uint4 hi, lo;
                splitq(*(const float4*)(v + j * 8), *(const float4*)(v + j * 8 + 4), hi, lo);
                *(uint4*)(szh + tok * 68 + pq * 8 + j * 4) = hi;
                *(uint4*)(szl + tok * 68 + pq * 8 + j * 4) = lo;
            }
        }
        __syncthreads();
    }

    // ===== stages 3-4: VAE reparam — fused mu+sg 8-chunk stream =====
#pragma unroll 1
    for (int mod = 0; mod < 2; ++mod) {
        const float* muW = mod ? mu_i_w : mu_t_w;
        const float* sgW = mod ? sg_i_w : sg_t_w;
        const float* muB = mod ? mu_i_b : mu_t_b;
        const float* sgB = mod ? sg_i_b : sg_t_b;
        const float* noi = mod ? i_noise : t_noise;
        uint32_t* szh = mod ? sYh : sXh;
        uint32_t* szl = mod ? sYl : sXl;
        float Dm[4][4];
        zeroD(D); zeroD(Dm);
        w_ldg(muW, Hd, 0, tid, wv);
        w_sts(WHB(0), WLB(0), tid, wv);
#pragma unroll 1
        for (int s = 0; s < 8; ++s) {
            int cur = s & 1, nxt = cur ^ 1;
            if (s + 1 < 8) {
                const float* Wn = (s + 1 < 4) ? muW : sgW;
                w_ldg(Wn, Hd, ((s + 1) & 3) * 32, tid, wv);
            }
            __syncthreads();
            if (s + 1 < 8) w_sts(WHB(nxt), WLB(nxt), tid, wv);
            mma_chunk(WHB(cur) + hb * 20, WLB(cur) + hb * 20,
                      szh + tb * 68 + (s & 3) * 16, szl + tb * 68 + (s & 3) * 16,
                      68, lane, (s < 4) ? Dm : D);
        }
        __syncthreads();
        stage_D(sWf, Dm, lane, hb, tb);
        __syncthreads();
        float mu16[16];
#pragma unroll
        for (int j = 0; j < 4; ++j)
            *(float4*)(mu16 + j * 4) = *(const float4*)(sWf + tok * 132 + pq * 16 + j * 4);
        __syncthreads();
        stage_D(sWf, D, lane, hb, tb);
        __syncthreads();
        {
            long n = n0 + tok;
#pragma unroll
            for (int j = 0; j < 2; ++j) {
                int o = pq * 16 + j * 8;
                float z[8];
#pragma unroll
                for (int k = 0; k < 8; ++k) {
                    float sg = sWf[tok * 132 + o + k];
                    z[k] = mu16[j * 8 + k] + muB[o + k] +
                           __expf(sg + sgB[o + k]) * noi[n * Hd + o + k];
                }
                uint4 hi, lo;
                splitq(*(const float4*)z, *(const float4*)(z + 4), hi, lo);
                *(uint4*)(szh + tok * 68 + pq * 8 + j * 4) = hi;
                *(uint4*)(szl + tok * 68 + pq * 8 + j * 4) = lo;
            }
        }
        __syncthreads();
    }

    // ===== stage 5: gating =====
    {
        int t = tok, e = pq;
        float dt = 0.f, di = 0.f;
        const uint32_t *xh = sXh + t * 68, *xl = sXl + t * 68;
        const uint32_t *yh = sYh + t * 68, *yl = sYl + t * 68;
        const float* gw = gate_w + e * Hd;
#pragma unroll 4
        for (int k4 = 0; k4 < 64; k4 += 4) {
#pragma unroll
            for (int j = 0; j < 4; ++j) {
                uint32_t a = xh[k4 + j], b = xl[k4 + j];
                uint32_t c = yh[k4 + j], d = yl[k4 + j];
                float zx0 = blo(a) + blo(b), zx1 = bhi(a) + bhi(b);
                float zy0 = blo(c) + blo(d), zy1 = bhi(c) + bhi(d);
                float w0 = gw[(k4 + j) * 2], w1 = gw[(k4 + j) * 2 + 1];
                dt = fmaf(zx0, w0, fmaf(zx1, w1, dt));
                di = fmaf(zy0, w0, fmaf(zy1, w1, di));
            }
        }
        sgt[t * 8 + e] = dt + gate_b[e];
        sgi[t * 8 + e] = di + gate_b[e];
    }
    __syncthreads();
    if (tid < TB) route8(sgt + tid * 8);
    else if (tid < 2 * TB) route8(sgi + (tid - TB) * 8);
    __syncthreads();

    // ===== stages 6-7: dense experts, 32-chunk stream, gate folded =====
#pragma unroll 1
    for (int mod = 0; mod < 2; ++mod) {
        const float* eW = mod ? iexp_w : texp_w;
        const float* eB = mod ? iexp_b : texp_b;
        const float* gs = mod ? sgi : sgt;
        uint32_t* szh = mod ? sYh : sXh;
        uint32_t* szl = mod ? sYl : sXl;
        float acc[4][4];
        zeroD(acc); zeroD(D);
        w_ldg(eW, Hd, 0, tid, wv);
        w_sts(WHB(0), WLB(0), tid, wv);
#pragma unroll 1
        for (int s = 0; s < 32; ++s) {
            int cur = s & 1, nxt = cur ^ 1;
            int e = s >> 2, c = s & 3;
            if (s + 1 < 32)
                w_ldg(eW + (long)((s + 1) >> 2) * Hd * Hd, Hd, ((s + 1) & 3) * 32, tid, wv);
            __syncthreads();
            if (s + 1 < 32) w_sts(WHB(nxt), WLB(nxt), tid, wv);
            mma_chunk(WHB(cur) + hb * 20, WLB(cur) + hb * 20,
                      szh + tb * 68 + c * 16, szl + tb * 68 + c * 16, 68, lane, D);
            if (c == 3) {
                int g = lane >> 2, q = lane & 3;
                float b0 = eB[e * Hd + hb + g], b1 = eB[e * Hd + hb + g + 8];
#pragma unroll
                for (int nt = 0; nt < 4; ++nt) {
                    int t0 = tb + nt * 8 + 2 * q;
                    float g0 = gs[t0 * 8 + e], g1 = gs[(t0 + 1) * 8 + e];
                    acc[nt][0] += g0 * (D[nt][0] + b0);
                    acc[nt][1] += g1 * (D[nt][1] + b0);
                    acc[nt][2] += g0 * (D[nt][2] + b1);
                    acc[nt][3] += g1 * (D[nt][3] + b1);
                    D[nt][0] = D[nt][1] = D[nt][2] = D[nt][3] = 0.f;
                }
            }
        }
        __syncthreads();
        stage_D(sWf, acc, lane, hb, tb);
        __syncthreads();
#pragma unroll
        for (int j = 0; j < 2; ++j) {
            uint4 hi, lo;
            splitq(*(const float4*)(sWf + tok * 132 + pq * 16 + j * 8),
                   *(const float4*)(sWf + tok * 132 + pq * 16 + j * 8 + 4), hi, lo);
            *(uint4*)(szh + tok * 68 + pq * 8 + j * 4) = hi;
            *(uint4*)(szl + tok * 68 + pq * 8 + j * 4) = lo;
        }
        __syncthreads();
    }

    // ===== stage 8: fusion + LN/relu + seq_emb =====
    zeroD(D);
    w_ldg(fus_w, 2 * Hd, 0, tid, wv);
    w_sts(WHB(0), WLB(0), tid, wv);
#pragma unroll 1
    for (int c = 0; c < 8; ++c) {
        int cur = c & 1, nxt = cur ^ 1;
        if (c + 1 < 8) w_ldg(fus_w, 2 * Hd, (c + 1) * 32, tid, wv);
        __syncthreads();
        if (c + 1 < 8) w_sts(WHB(nxt), WLB(nxt), tid, wv);
        const uint32_t* Bh = (c < 4) ? sXh + c * 16 : sYh + (c - 4) * 16;
        const uint32_t* Bl = (c < 4) ? sXl + c * 16 : sYl + (c - 4) * 16;
        mma_chunk(WHB(cur) + hb * 20, WLB(cur) + hb * 20,
                  Bh + tb * 68, Bl + tb * 68, 68, lane, D);
    }
    __syncthreads();
    stage_D(sWf, D, lane, hb, tb);
    __syncthreads();
    {
        long n = n0 + tok;
        float v[16]; float s = 0.f, s2 = 0.f;
#pragma unroll
        for (int j = 0; j < 4; ++j) {
            float4 a = *(const float4*)(sWf + tok * 132 + pq * 16 + j * 4);
            float4 b = *(const float4*)(fus_b + pq * 16 + j * 4);
            v[j*4+0] = a.x + b.x; v[j*4+1] = a.y + b.y;
            v[j*4+2] = a.z + b.z; v[j*4+3] = a.w + b.w;
#pragma unroll
            for (int k = 0; k < 4; ++k) { s += v[j*4+k]; s2 += v[j*4+k] * v[j*4+k]; }
        }
        s  += __shfl_xor_sync(0xffffffffu, s, 1);  s  += __shfl_xor_sync(0xffffffffu, s, 2);
        s  += __shfl_xor_sync(0xffffffffu, s, 4);
        s2 += __shfl_xor_sync(0xffffffffu, s2, 1); s2 += __shfl_xor_sync(0xffffffffu, s2, 2);
        s2 += __shfl_xor_sync(0xffffffffu, s2, 4);
        float mean = s * (1.f / Hd);
        float var  = s2 * (1.f / Hd) - mean * mean;
        float inv  = rsqrtf(var + 1e-5f);
        int id = sids[tok], pos = (int)(n % Ld);
        float w[16]; float t1 = 0.f, t2 = 0.f;
#pragma unroll
        for (int j = 0; j < 4; ++j) {
            float4 a = *(const float4*)(item_table + (long)id * Hd + pq * 16 + j * 4);
            float4 b = *(const float4*)(pos_table + pos * Hd + pq * 16 + j * 4);
            w[j*4+0] = a.x + b.x; w[j*4+1] = a.y + b.y;
            w[j*4+2] = a.z + b.z; w[j*4+3] = a.w + b.w;
#pragma unroll
            for (int k = 0; k < 4; ++k) { t1 += w[j*4+k]; t2 += w[j*4+k] * w[j*4+k]; }
        }
        t1 += __shfl_xor_sync(0xffffffffu, t1, 1); t1 += __shfl_xor_sync(0xffffffffu, t1, 2);
        t1 += __shfl_xor_sync(0xffffffffu, t1, 4);
        t2 += __shfl_xor_sync(0xffffffffu, t2, 1); t2 += __shfl_xor_sync(0xffffffffu, t2, 2);
        t2 += __shfl_xor_sync(0xffffffffu, t2, 4);
        float mean2 = t1 * (1.f / Hd);
        float var2  = t2 * (1.f / Hd) - mean2 * mean2;
        float inv2  = rsqrtf(var2 + 1e-12f);
#pragma unroll
        for (int j = 0; j < 4; ++j) {
            int o = pq * 16 + j * 4;
            float4 lw  = *(const float4*)(fus_ln_w + o);
            float4 lb  = *(const float4*)(fus_ln_b + o);
            float4 slw = *(const float4*)(ln_w + o);
            float4 slb = *(const float4*)(ln_b + o);
            float4 r;
            r.x = fmaxf((v[j*4+0] - mean) * inv * lw.x + lb.x, 0.f) + (w[j*4+0] - mean2) * inv2 * slw.x + slb.x;
            r.y = fmaxf((v[j*4+1] - mean) * inv * lw.y + lb.y, 0.f) + (w[j*4+1] - mean2) * inv2 * slw.y + slb.y;
            r.z = fmaxf((v[j*4+2] - mean) * inv * lw.z + lb.z, 0.f) + (w[j*4+2] - mean2) * inv2 * slw.z + slb.z;
            r.w = fmaxf((v[j*4+3] - mean) * inv * lw.w + lb.w, 0.f) + (w[j*4+3] - mean2) * inv2 * slw.w + slb.w;
            *(float4*)(out + n * Hd + o) = r;
        }
    }
}

extern "C" void kernel_launch(void* const* d_in, const int* in_sizes, int n_in,
                              void* d_out, int out_size) {
    (void)in_sizes; (void)n_in; (void)out_size;
    size_t smem = SMEMU * sizeof(uint32_t);
    cudaFuncSetAttribute(sasrec_mma_kernel,
                         cudaFuncAttributeMaxDynamicSharedMemorySize, (int)smem);
    sasrec_mma_kernel<<<NTOK / TB, NTH, smem>>>(
        (const int*)d_in[0], (const float*)d_in[1], (const float*)d_in[2],
        (const float*)d_in[3], (const float*)d_in[4], (const float*)d_in[5],
        (const float*)d_in[6], (const float*)d_in[7], (const float*)d_in[8],
        (const float*)d_in[9], (const float*)d_in[10], (const float*)d_in[11],
        (const float*)d_in[12], (const float*)d_in[13], (const float*)d_in[14],
        (const float*)d_in[15], (const float*)d_in[16], (const float*)d_in[17],
        (const float*)d_in[18], (const float*)d_in[19], (const float*)d_in[20],
        (const float*)d_in[21], (const float*)d_in[22], (const float*)d_in[23],
        (const float*)d_in[24], (const float*)d_in[25], (const float*)d_in[26],
        (const float*)d_in[27], (const float*)d_in[28], (const float*)d_in[29],
        (const float*)d_in[30], (float*)d_out);
}

// round 12
// speedup vs baseline: 1.1847x; 1.1847x over previous
#include <cuda_runtime.h>
#include <math.h>
#include <stdint.h>

#define Hd 128
#define Ld 200
#define DTd 768
#define DId 512
#define NTOK 25600
#define TB 64
#define NTH 512

// chunk-table bases (each chunk = 128h x 32k)
#define C_TEXT 0
#define C_IMG  24
#define C_MUT  40
#define C_SGT  44
#define C_MUI  48
#define C_SGI  52
#define C_TEXP 56
#define C_IEXP 88
#define C_FUS  120
#define NCHUNK 128

__device__ uint4 g_whi[NCHUNK * 512];
__device__ uint4 g_wlo[NCHUNK * 512];

// smem layout (u32 units); W stride 24, A stride 20, X/Y stride 68
#define O_WH 0
#define O_WL 3072
#define O_AH 6144
#define O_AL 7424
#define O_XH 8704
#define O_XL 13056
#define O_YH 17408
#define O_YL 21760
#define O_GT 26112
#define O_GI 26624
#define O_ID 27136
#define SMEMU 27200   // 108800 B

__device__ __forceinline__ uint32_t cvt2(float lo, float hi) {
    uint32_t r;
    asm("cvt.rn.bf16x2.f32 %0, %1, %2;" : "=r"(r) : "f"(hi), "f"(lo));
    return r;
}
__device__ __forceinline__ float blo(uint32_t u) { return __uint_as_float(u << 16); }
__device__ __forceinline__ float bhi(uint32_t u) { return __uint_as_float(u & 0xffff0000u); }

__device__ __forceinline__ void splitq(float4 a, float4 b, uint4& h, uint4& l) {
    h.x = cvt2(a.x, a.y); l.x = cvt2(a.x - blo(h.x), a.y - bhi(h.x));
    h.y = cvt2(a.z, a.w); l.y = cvt2(a.z - blo(h.y), a.w - bhi(h.y));
    h.z = cvt2(b.x, b.y); l.z = cvt2(b.x - blo(h.z), b.y - bhi(h.z));
    h.w = cvt2(b.z, b.w); l.w = cvt2(b.z - blo(h.w), b.w - bhi(h.w));
}

__device__ __forceinline__ void MMA(float* d, uint32_t a0, uint32_t a1, uint32_t a2, uint32_t a3,
                                    uint32_t b0, uint32_t b1) {
    asm volatile("mma.sync.aligned.m16n8k16.row.col.f32.bf16.bf16.f32 "
                 "{%0,%1,%2,%3},{%4,%5,%6,%7},{%8,%9},{%0,%1,%2,%3};"
                 : "+f"(d[0]), "+f"(d[1]), "+f"(d[2]), "+f"(d[3])
                 : "r"(a0), "r"(a1), "r"(a2), "r"(a3), "r"(b0), "r"(b1));
}

__device__ __forceinline__ void zeroD(float D[4][4]) {
#pragma unroll
    for (int n = 0; n < 4; ++n)
#pragma unroll
        for (int j = 0; j < 4; ++j) D[n][j] = 0.f;
}

// ===== prep: split+permute all weights once per launch =====
__global__ void prep_kernel(
    const float* __restrict__ fc_text_w, const float* __restrict__ fc_img_w,
    const float* __restrict__ mu_t_w, const float* __restrict__ sg_t_w,
    const float* __restrict__ mu_i_w, const float* __restrict__ sg_i_w,
    const float* __restrict__ texp_w, const float* __restrict__ iexp_w,
    const float* __restrict__ fus_w)
{
    int chunk = blockIdx.x, tid = threadIdx.x;
    const float* W; int ldw, kc;
    if (chunk < C_IMG)       { W = fc_text_w; ldw = DTd; kc = chunk * 32; }
    else if (chunk < C_MUT)  { W = fc_img_w;  ldw = DId; kc = (chunk - C_IMG) * 32; }
    else if (chunk < C_SGT)  { W = mu_t_w; ldw = Hd; kc = (chunk - C_MUT) * 32; }
    else if (chunk < C_MUI)  { W = sg_t_w; ldw = Hd; kc = (chunk - C_SGT) * 32; }
    else if (chunk < C_SGI)  { W = mu_i_w; ldw = Hd; kc = (chunk - C_MUI) * 32; }
    else if (chunk < C_TEXP) { W = sg_i_w; ldw = Hd; kc = (chunk - C_SGI) * 32; }
    else if (chunk < C_IEXP) { W = texp_w + (long)((chunk - C_TEXP) >> 2) * Hd * Hd; ldw = Hd; kc = ((chunk - C_TEXP) & 3) * 32; }
    else if (chunk < C_FUS)  { W = iexp_w + (long)((chunk - C_IEXP) >> 2) * Hd * Hd; ldw = Hd; kc = ((chunk - C_IEXP) & 3) * 32; }
    else                     { W = fus_w; ldw = 2 * Hd; kc = (chunk - C_FUS) * 32; }
    int h = tid >> 2, q = tid & 3;
    uint32_t hv[4], lv[4];
#pragma unroll
    for (int j = 0; j < 4; ++j) {
        int p = q * 4 + j;   // physical pair slot
        int lp = (p < 8) ? ((p & 1) ? 4 + (p >> 1) : (p >> 1))
                         : ((p & 1) ? 12 + ((p - 8) >> 1) : 8 + ((p - 8) >> 1));
        const float* s = W + (long)h * ldw + kc + lp * 2;
        float x = s[0], y = s[1];
        uint32_t hi = cvt2(x, y);
        hv[j] = hi;
        lv[j] = cvt2(x - blo(hi), y - bhi(hi));
    }
    g_whi[chunk * 512 + tid] = make_uint4(hv[0], hv[1], hv[2], hv[3]);
    g_wlo[chunk * 512 + tid] = make_uint4(lv[0], lv[1], lv[2], lv[3]);
}

// ===== hot-kernel weight path: pure copy =====
__device__ __forceinline__ void w_ldg2(int ci, int tid, uint4& wh, uint4& wl) {
    wh = g_whi[ci * 512 + tid];
    wl = g_wlo[ci * 512 + tid];
}
__device__ __forceinline__ void w_sts2(uint32_t* sWh, uint32_t* sWl, int tid,
                                       const uint4& wh, const uint4& wl) {
    int h = tid >> 2, q = tid & 3;
    *(uint4*)(sWh + h * 24 + q * 4) = wh;
    *(uint4*)(sWl + h * 24 + q * 4) = wl;
}
// gathered activation chunk 64tok x 32k (first 256 threads), stride 20
__device__ __forceinline__ void ga_ldg(const float* __restrict__ T, int ldw, int kc,
                                       const int* sids, int tid, float4 v[2]) {
    if (tid < 256) {
        int tok = tid >> 2, q = tid & 3;
        const float* p = T + (long)sids[tok] * ldw + kc + q * 8;
        v[0] = *(const float4*)p;
        v[1] = *(const float4*)(p + 4);
    }
}
__device__ __forceinline__ void ga_sts(uint32_t* sAh, uint32_t* sAl, int tid, const float4 v[2]) {
    if (tid < 256) {
        int tok = tid >> 2, q = tid & 3;
        uint4 hi, lo;
        splitq(v[0], v[1], hi, lo);
        *(uint4*)(sAh + tok * 20 + q * 4) = hi;
        *(uint4*)(sAl + tok * 20 + q * 4) = lo;
    }
}

// one KC=32 chunk: warp tile 16h x 32tok, 3-limb; A pairs interleaved (uint2 loads)
__device__ __forceinline__ void mma_chunk(const uint32_t* __restrict__ Wh, const uint32_t* __restrict__ Wl,
                                          const uint32_t* __restrict__ Bh, const uint32_t* __restrict__ Bl,
                                          int bst, int lane, float D[4][4]) {
    int g = lane >> 2, q = lane & 3;
#pragma unroll
    for (int kt = 0; kt < 2; ++kt) {
        int o = kt * 8 + q;
        int ap = kt * 8 + 2 * q;
        uint2 h0 = *(const uint2*)(Wh + g * 24 + ap);
        uint2 h1 = *(const uint2*)(Wh + (g + 8) * 24 + ap);
        uint2 l0 = *(const uint2*)(Wl + g * 24 + ap);
        uint2 l1 = *(const uint2*)(Wl + (g + 8) * 24 + ap);
#pragma unroll
        for (int nt = 0; nt < 4; ++nt) {
            const uint32_t* bp = Bh + (nt * 8 + g) * bst + o;
            const uint32_t* bq = Bl + (nt * 8 + g) * bst + o;
            uint32_t b0 = bp[0], b1 = bp[4];
            uint32_t c0 = bq[0], c1 = bq[4];
            MMA(D[nt], h0.x, h1.x, h0.y, h1.y, b0, b1);
            MMA(D[nt], h0.x, h1.x, h0.y, h1.y, c0, c1);
            MMA(D[nt], l0.x, l1.x, l0.y, l1.y, b0, b1);
        }
    }
}

__device__ __forceinline__ void stage_D(float* sWf, float D[4][4], int lane, int hb, int tb) {
    int g = lane >> 2, q = lane & 3;
#pragma unroll
    for (int nt = 0; nt < 4; ++nt) {
        int t0 = tb + nt * 8 + 2 * q;
        float* p0 = sWf + t0 * 132 + hb + g;
        float* p1 = sWf + (t0 + 1) * 132 + hb + g;
        p0[0] = D[nt][0]; p1[0] = D[nt][1]; p0[8] = D[nt][2]; p1[8] = D[nt][3];
    }
}

__device__ __forceinline__ void route8(float* g) {
    float m = g[0];
#pragma unroll
    for (int e = 1; e < 8; ++e) m = fmaxf(m, g[e]);
    float ex[8]; float s = 0.f;
#pragma unroll
    for (int e = 0; e < 8; ++e) { ex[e] = __expf(g[e] - m); s += ex[e]; }
    float inv = 1.f / s;
#pragma unroll
    for (int e = 0; e < 8; ++e) ex[e] *= inv;
    int i1 = 0; float w1 = ex[0];
#pragma unroll
    for (int e = 1; e < 8; ++e) if (ex[e] > w1) { w1 = ex[e]; i1 = e; }
    int i2 = -1; float w2 = -1.f;
#pragma unroll
    for (int e = 0; e < 8; ++e) if (e != i1 && ex[e] > w2) { w2 = ex[e]; i2 = e; }
    float den = 1.f / (w1 + w2 + 1e-8f);
#pragma unroll
    for (int e = 0; e < 8; ++e)
        g[e] = (e == i1) ? w1 * den : ((e == i2) ? w2 * den : 0.f);
}

__global__ __launch_bounds__(NTH, 1)
void sasrec_mma_kernel(
    const int*   __restrict__ input_ids,
    const float* __restrict__ t_noise,   const float* __restrict__ i_noise,
    const float* __restrict__ item_table,const float* __restrict__ pos_table,
    const float* __restrict__ text_table,const float* __restrict__ img_table,
    const float* __restrict__ fc_text_b, const float* __restrict__ fc_img_b,
    const float* __restrict__ ln_w,      const float* __restrict__ ln_b,
    const float* __restrict__ mu_t_b,    const float* __restrict__ sg_t_b,
    const float* __restrict__ mu_i_b,    const float* __restrict__ sg_i_b,
    const float* __restrict__ gate_w,    const float* __restrict__ gate_b,
    const float* __restrict__ texp_b,    const float* __restrict__ iexp_b,
    const float* __restrict__ fus_b,
    const float* __restrict__ fus_ln_w,  const float* __restrict__ fus_ln_b,
    float*       __restrict__ out)
{
    extern __shared__ uint32_t su[];
    float* sWf = (float*)su;      // staging aliases W+A region (8704 u32 >= 8448 needed)
    uint32_t *sWh = su + O_WH, *sWl = su + O_WL;
    uint32_t *sAh = su + O_AH, *sAl = su + O_AL;
    uint32_t *sXh = su + O_XH, *sXl = su + O_XL;
    uint32_t *sYh = su + O_YH, *sYl = su + O_YL;
    float *sgt = (float*)(su + O_GT), *sgi = (float*)(su + O_GI);
    int* sids = (int*)(su + O_ID);

    const int tid = threadIdx.x, lane = tid & 31, wid = tid >> 5;
    const int hb = (wid & 7) * 16;
    const int tb = (wid >> 3) * 32;
    const int n0 = blockIdx.x * TB;
    const int tok = tid >> 3, pq = tid & 7;

    if (tid < TB) sids[tid] = input_ids[n0 + tid];
    __syncthreads();

    float D[4][4];
    uint4 wh, wl;
    float4 av[2];

    // ===== stages 1-2: modality embeddings =====
#pragma unroll 1
    for (int mod = 0; mod < 2; ++mod) {
        const float* tbl = mod ? img_table : text_table;
        const float* Bb  = mod ? fc_img_b : fc_text_b;
        const int Kd = mod ? DId : DTd;
        const int cb = mod ? C_IMG : C_TEXT;
        uint32_t* szh = mod ? sYh : sXh;
        uint32_t* szl = mod ? sYl : sXl;
        zeroD(D);
        w_ldg2(cb, tid, wh, wl);
        ga_ldg(tbl, Kd, 0, sids, tid, av);
        const int nck = Kd / 32;
#pragma unroll 1
        for (int c = 0; c < nck; ++c) {
            w_sts2(sWh, sWl, tid, wh, wl);
            ga_sts(sAh, sAl, tid, av);
            __syncthreads();
            if (c + 1 < nck) {
                w_ldg2(cb + c + 1, tid, wh, wl);
                ga_ldg(tbl, Kd, (c + 1) * 32, sids, tid, av);
            }
            mma_chunk(sWh + hb * 24, sWl + hb * 24,
                      sAh + tb * 20, sAl + tb * 20, 20, lane, D);
            __syncthreads();
        }
        stage_D(sWf, D, lane, hb, tb);
        __syncthreads();
        {
            float v[16]; float ss = 0.f;
#pragma unroll
            for (int j = 0; j < 4; ++j) {
                float4 a = *(const float4*)(sWf + tok * 132 + pq * 16 + j * 4);
                float4 b = *(const float4*)(Bb + pq * 16 + j * 4);
                v[j*4+0] = a.x + b.x; v[j*4+1] = a.y + b.y;
                v[j*4+2] = a.z + b.z; v[j*4+3] = a.w + b.w;
#pragma unroll
                for (int k = 0; k < 4; ++k) ss += v[j*4+k] * v[j*4+k];
            }
            ss += __shfl_xor_sync(0xffffffffu, ss, 1);
            ss += __shfl_xor_sync(0xffffffffu, ss, 2);
            ss += __shfl_xor_sync(0xffffffffu, ss, 4);
            float sc = 1.f / fmaxf(sqrtf(ss), 1e-12f);
#pragma unroll
            for (int j = 0; j < 16; ++j) v[j] *= sc;
#pragma unroll
            for (int j = 0; j < 2; ++j) {
                uint4 hi, lo;
                splitq(*(const float4*)(v + j * 8), *(const float4*)(v + j * 8 + 4), hi, lo);
                *(uint4*)(szh + tok * 68 + pq * 8 + j * 4) = hi;
                *(uint4*)(szl + tok * 68 + pq * 8 + j * 4) = lo;
            }
        }
        __syncthreads();
    }

    // ===== stages 3-4: VAE reparam (mu via out scratch) =====
#pragma unroll 1
    for (int mod = 0; mod < 2; ++mod) {
        const int cmu = mod ? C_MUI : C_MUT;
        const int csg = mod ? C_SGI : C_SGT;
        const float* muB = mod ? mu_i_b : mu_t_b;
        const float* sgB = mod ? sg_i_b : sg_t_b;
        const float* noi = mod ? i_noise : t_noise;
        uint32_t* szh = mod ? sYh : sXh;
        uint32_t* szl = mod ? sYl : sXl;
        zeroD(D);
        w_ldg2(cmu, tid, wh, wl);
#pragma unroll 1
        for (int c = 0; c < 4; ++c) {
            w_sts2(sWh, sWl, tid, wh, wl);
            __syncthreads();
            w_ldg2((c < 3) ? (cmu + c + 1) : csg, tid, wh, wl);
            mma_chunk(sWh + hb * 24, sWl + hb * 24,
                      szh + tb * 68 + c * 16, szl + tb * 68 + c * 16, 68, lane, D);
            __syncthreads();
        }
        stage_D(sWf, D, lane, hb, tb);
        __syncthreads();
#pragma unroll
        for (int j = 0; j < 2; ++j) {
            int idx = tid + j * NTH;
            int t = idx >> 4, q = idx & 15;
            float4 a = *(const float4*)(sWf + t * 132 + q * 8);
            float4 b = *(const float4*)(sWf + t * 132 + q * 8 + 4);
            float* p = out + (long)(n0 + t) * Hd + q * 8;
            *(float4*)p = a; *(float4*)(p + 4) = b;
        }
        __syncthreads();
        zeroD(D);
#pragma unroll 1
        for (int c = 0; c < 4; ++c) {
            w_sts2(sWh, sWl, tid, wh, wl);
            __syncthreads();
            if (c < 3) w_ldg2(csg + c + 1, tid, wh, wl);
            mma_chunk(sWh + hb * 24, sWl + hb * 24,
                      szh + tb * 68 + c * 16, szl + tb * 68 + c * 16, 68, lane, D);
            __syncthreads();
        }
        stage_D(sWf, D, lane, hb, tb);
        __syncthreads();
        {
            long n = n0 + tok;
#pragma unroll
            for (int j = 0; j < 2; ++j) {
                int o = pq * 16 + j * 8;
                float z[8];
#pragma unroll
                for (int k = 0; k < 8; ++k) {
                    float sg = sWf[tok * 132 + o + k];
                    float mu = out[n * Hd + o + k];
                    z[k] = mu + muB[o + k] + __expf(sg + sgB[o + k]) * noi[n * Hd + o + k];
                }
                uint4 hi, lo;
                splitq(*(const float4*)z, *(const float4*)(z + 4), hi, lo);
                *(uint4*)(szh + tok * 68 + pq * 8 + j * 4) = hi;
                *(uint4*)(szl + tok * 68 + pq * 8 + j * 4) = lo;
            }
        }
        __syncthreads();
    }

    // ===== stage 5: gating =====
    {
        int t = tok, e = pq;
        float dt = 0.f, di = 0.f;
        const uint32_t *xh = sXh + t * 68, *xl = sXl + t * 68;
        const uint32_t *yh = sYh + t * 68, *yl = sYl + t * 68;
        const float* gw = gate_w + e * Hd;
#pragma unroll 4
        for (int k4 = 0; k4 < 64; k4 += 4) {
#pragma unroll
            for (int j = 0; j < 4; ++j) {
                uint32_t a = xh[k4 + j], b = xl[k4 + j];
                uint32_t c = yh[k4 + j], d = yl[k4 + j];
                float zx0 = blo(a) + blo(b), zx1 = bhi(a) + bhi(b);
                float zy0 = blo(c) + blo(d), zy1 = bhi(c) + bhi(d);
                float w0 = gw[(k4 + j) * 2], w1 = gw[(k4 + j) * 2 + 1];
                dt = fmaf(zx0, w0, fmaf(zx1, w1, dt));
                di = fmaf(zy0, w0, fmaf(zy1, w1, di));
            }
        }
        sgt[t * 8 + e] = dt + gate_b[e];
        sgi[t * 8 + e] = di + gate_b[e];
    }
    __syncthreads();
    if (tid < TB) route8(sgt + tid * 8);
    else if (tid < 2 * TB) route8(sgi + (tid - TB) * 8);
    __syncthreads();

    // ===== stages 6-7: dense experts, gate folded =====
#pragma unroll 1
    for (int mod = 0; mod < 2; ++mod) {
        const int cb = mod ? C_IEXP : C_TEXP;
        const float* eB = mod ? iexp_b : texp_b;
        const float* gs = mod ? sgi : sgt;
        uint32_t* szh = mod ? sYh : sXh;
        uint32_t* szl = mod ? sYl : sXl;
        float acc[4][4];
        zeroD(acc); zeroD(D);
        w_ldg2(cb, tid, wh, wl);
#pragma unroll 1
        for (int s = 0; s < 32; ++s) {
            int e = s >> 2, c = s & 3;
            w_sts2(sWh, sWl, tid, wh, wl);
            __syncthreads();
            if (s + 1 < 32) w_ldg2(cb + s + 1, tid, wh, wl);
            mma_chunk(sWh + hb * 24, sWl + hb * 24,
                      szh + tb * 68 + c * 16, szl + tb * 68 + c * 16, 68, lane, D);
            __syncthreads();
            if (c == 3) {
                int g = lane >> 2, q = lane & 3;
                float b0 = eB[e * Hd + hb + g], b1 = eB[e * Hd + hb + g + 8];
#pragma unroll
                for (int nt = 0; nt < 4; ++nt) {
                    int t0 = tb + nt * 8 + 2 * q;
                    float g0 = gs[t0 * 8 + e], g1 = gs[(t0 + 1) * 8 + e];
                    acc[nt][0] += g0 * (D[nt][0] + b0);
                    acc[nt][1] += g1 * (D[nt][1] + b0);
                    acc[nt][2] += g0 * (D[nt][2] + b1);
                    acc[nt][3] += g1 * (D[nt][3] + b1);
                    D[nt][0] = D[nt][1] = D[nt][2] = D[nt][3] = 0.f;
                }
            }
        }
        stage_D(sWf, acc, lane, hb, tb);
        __syncthreads();
#pragma unroll
        for (int j = 0; j < 2; ++j) {
            uint4 hi, lo;
            splitq(*(const float4*)(sWf + tok * 132 + pq * 16 + j * 8),
                   *(const float4*)(sWf + tok * 132 + pq * 16 + j * 8 + 4), hi, lo);
            *(uint4*)(szh + tok * 68 + pq * 8 + j * 4) = hi;
            *(uint4*)(szl + tok * 68 + pq * 8 + j * 4) = lo;
        }
        __syncthreads();
    }

    // ===== stage 8: fusion + LN/relu + seq_emb =====
    zeroD(D);
    w_ldg2(C_FUS, tid, wh, wl);
#pragma unroll 1
    for (int c = 0; c < 8; ++c) {
        w_sts2(sWh, sWl, tid, wh, wl);
        __syncthreads();
        if (c + 1 < 8) w_ldg2(C_FUS + c + 1, tid, wh, wl);
        const uint32_t* Bh = (c < 4) ? sXh + c * 16 : sYh + (c - 4) * 16;
        const uint32_t* Bl = (c < 4) ? sXl + c * 16 : sYl + (c - 4) * 16;
        mma_chunk(sWh + hb * 24, sWl + hb * 24, Bh + tb * 68, Bl + tb * 68, 68, lane, D);
        __syncthreads();
    }
    stage_D(sWf, D, lane, hb, tb);
    __syncthreads();
    {
        long n = n0 + tok;
        float v[16]; float s = 0.f, s2 = 0.f;
#pragma unroll
        for (int j = 0; j < 4; ++j) {
            float4 a = *(const float4*)(sWf + tok * 132 + pq * 16 + j * 4);
            float4 b = *(const float4*)(fus_b + pq * 16 + j * 4);
            v[j*4+0] = a.x + b.x; v[j*4+1] = a.y + b.y;
            v[j*4+2] = a.z + b.z; v[j*4+3] = a.w + b.w;
#pragma unroll
            for (int k = 0; k < 4; ++k) { s += v[j*4+k]; s2 += v[j*4+k] * v[j*4+k]; }
        }
        s  += __shfl_xor_sync(0xffffffffu, s, 1);  s  += __shfl_xor_sync(0xffffffffu, s, 2);
        s  += __shfl_xor_sync(0xffffffffu, s, 4);
        s2 += __shfl_xor_sync(0xffffffffu, s2, 1); s2 += __shfl_xor_sync(0xffffffffu, s2, 2);
        s2 += __shfl_xor_sync(0xffffffffu, s2, 4);
        float mean = s * (1.f / Hd);
        float var  = s2 * (1.f / Hd) - mean * mean;
        float inv  = rsqrtf(var + 1e-5f);
        int id = sids[tok], pos = (int)(n % Ld);
        float w[16]; float t1 = 0.f, t2 = 0.f;
#pragma unroll
        for (int j = 0; j < 4; ++j) {
            float4 a = *(const float4*)(item_table + (long)id * Hd + pq * 16 + j * 4);
            float4 b = *(const float4*)(pos_table + pos * Hd + pq * 16 + j * 4);
            w[j*4+0] = a.x + b.x; w[j*4+1] = a.y + b.y;
            w[j*4+2] = a.z + b.z; w[j*4+3] = a.w + b.w;
#pragma unroll
            for (int k = 0; k < 4; ++k) { t1 += w[j*4+k]; t2 += w[j*4+k] * w[j*4+k]; }
        }
        t1 += __shfl_xor_sync(0xffffffffu, t1, 1); t1 += __shfl_xor_sync(0xffffffffu, t1, 2);
        t1 += __shfl_xor_sync(0xffffffffu, t1, 4);
        t2 += __shfl_xor_sync(0xffffffffu, t2, 1); t2 += __shfl_xor_sync(0xffffffffu, t2, 2);
        t2 += __shfl_xor_sync(0xffffffffu, t2, 4);
        float mean2 = t1 * (1.f / Hd);
        float var2  = t2 * (1.f / Hd) - mean2 * mean2;
        float inv2  = rsqrtf(var2 + 1e-12f);
#pragma unroll
        for (int j = 0; j < 4; ++j) {
            int o = pq * 16 + j * 4;
            float4 lw  = *(const float4*)(fus_ln_w + o);
            float4 lb  = *(const float4*)(fus_ln_b + o);
            float4 slw = *(const float4*)(ln_w + o);
            float4 slb = *(const float4*)(ln_b + o);
            float4 r;
            r.x = fmaxf((v[j*4+0] - mean) * inv * lw.x + lb.x, 0.f) + (w[j*4+0] - mean2) * inv2 * slw.x + slb.x;
            r.y = fmaxf((v[j*4+1] - mean) * inv * lw.y + lb.y, 0.f) + (w[j*4+1] - mean2) * inv2 * slw.y + slb.y;
            r.z = fmaxf((v[j*4+2] - mean) * inv * lw.z + lb.z, 0.f) + (w[j*4+2] - mean2) * inv2 * slw.z + slb.z;
            r.w = fmaxf((v[j*4+3] - mean) * inv * lw.w + lb.w, 0.f) + (w[j*4+3] - mean2) * inv2 * slw.w + slb.w;
            *(float4*)(out + n * Hd + o) = r;
        }
    }
}

extern "C" void kernel_launch(void* const* d_in, const int* in_sizes, int n_in,
                              void* d_out, int out_size) {
    (void)in_sizes; (void)n_in; (void)out_size;
    prep_kernel<<<NCHUNK, 512>>>(
        (const float*)d_in[7], (const float*)d_in[9],
        (const float*)d_in[13], (const float*)d_in[15],
        (const float*)d_in[17], (const float*)d_in[19],
        (const float*)d_in[23], (const float*)d_in[25],
        (const float*)d_in[27]);
    size_t smem = SMEMU * sizeof(uint32_t);
    cudaFuncSetAttribute(sasrec_mma_kernel,
                         cudaFuncAttributeMaxDynamicSharedMemorySize, (int)smem);
    sasrec_mma_kernel<<<NTOK / TB, NTH, smem>>>(
        (const int*)d_in[0], (const float*)d_in[1], (const float*)d_in[2],
        (const float*)d_in[3], (const float*)d_in[4], (const float*)d_in[5],
        (const float*)d_in[6],
        (const float*)d_in[8], (const float*)d_in[10],
        (const float*)d_in[11], (const float*)d_in[12],
        (const float*)d_in[14], (const float*)d_in[16],
        (const float*)d_in[18], (const float*)d_in[20],
        (const float*)d_in[21], (const float*)d_in[22],
        (const float*)d_in[24], (const float*)d_in[26],
        (const float*)d_in[28], (const float*)d_in[29],
        (const float*)d_in[30], (float*)d_out);
}